// round 14
// baseline (speedup 1.0000x reference)
#include <cuda_runtime.h>
#include <cstdint>

#define IMG_D 224
#define HW (IMG_D * IMG_D)
#define NBATCH 64

#define R_TILE 8
#define HALO 4
#define WMAX (R_TILE + 2 * HALO)        // 16 rows staged
#define TILES_PER_IMG (IMG_D / R_TILE)  // 28
#define TPB 448                         // 2 sub-rows x 224 cols
#define ROWSUB 2
#define PXT (R_TILE / ROWSUB)           // 4 pixels per thread
#define PLANE_W (WMAX * IMG_D)          // 3584 floats
#define PLANE_BYTES (PLANE_W * 4)       // 14336 B
#define SMEM_BYTES (6 * PLANE_BYTES)    // 86016 B -> 2 blocks/SM

// R11 geometry with PER-PLANE mbarriers (6): channel-c compute starts as
// soon as its single 14KB plane lands (vs waiting for the full 43KB image
// group). Per image, a compact per-pixel state (weights, two word offsets,
// dy01, ok) is computed BEFORE any wait, so each channel section is a pure
// wait -> 4xLDS -> FFMA burst. offf+dy01 addressing handles iyc==iyf
// naturally (dy01=0 loads the same word). Fallback pixels store global
// word offsets in the same state. Arithmetic order per element is
// unchanged (im1 term then im2 term) -> bit-identical result.
__global__ __launch_bounds__(TPB)
void view_morph14_kernel(
    const float* __restrict__ im1,
    const float* __restrict__ im2,
    const float* __restrict__ C,
    const float* __restrict__ M1,
    const float* __restrict__ M2,
    float* __restrict__ out)
{
    extern __shared__ float sp[];
    __shared__ alignas(8) uint64_t mbar_storage[6];

    int blk = blockIdx.x;
    int n = blk / TILES_PER_IMG;
    int tile = blk - n * TILES_PER_IMG;
    int r0 = tile * R_TILE;

    int wl = max(0, r0 - HALO);
    int wh = min(IMG_D - 1, r0 + R_TILE - 1 + HALO);
    int wc = wh - wl + 1;

    int tid = threadIdx.x;
    int col = tid % IMG_D;
    int rsub = tid / IMG_D;

    const float* b1 = im1 + (size_t)n * 3 * HW;
    const float* b2 = im2 + (size_t)n * 3 * HW;

    uint32_t mb0  = (uint32_t)__cvta_generic_to_shared(&mbar_storage[0]);
    uint32_t spb0 = (uint32_t)__cvta_generic_to_shared(sp);

    if (tid == 0) {
        #pragma unroll
        for (int i = 0; i < 6; i++)
            asm volatile("mbarrier.init.shared.b64 [%0], 1;"
                         :: "r"(mb0 + i * 8) : "memory");
    }
    __syncthreads();

    if (tid == 0) {
        uint32_t copy_bytes = (uint32_t)(wc * IMG_D * 4);
        #pragma unroll
        for (int pl = 0; pl < 6; pl++) {
            uint32_t mb = mb0 + pl * 8;
            asm volatile("mbarrier.arrive.expect_tx.shared.b64 _, [%0], %1;"
                         :: "r"(mb), "r"(copy_bytes) : "memory");
            const float* src = (pl < 3 ? b1 + pl * HW : b2 + (pl - 3) * HW)
                               + wl * IMG_D;
            asm volatile(
                "cp.async.bulk.shared::cta.global.mbarrier::complete_tx::bytes"
                " [%0], [%1], %2, [%3];"
                :: "r"(spb0 + pl * PLANE_BYTES), "l"(src),
                   "r"(copy_bytes), "r"(mb) : "memory");
        }
    }

    // ── prefetch C/M while TMA runs ──
    const float* Cn  = C  + (size_t)n * 2 * HW;
    const float* M1n = M1 + (size_t)n * HW;
    const float* M2n = M2 + (size_t)n * HW;

    float cx[PXT], cy[PXT], m1v[PXT], m2v[PXT];
    #pragma unroll
    for (int k = 0; k < PXT; k++) {
        int r = r0 + rsub + k * ROWSUB;
        int p = r * IMG_D + col;
        cx[k]  = __ldg(Cn + p);
        cy[k]  = __ldg(Cn + HW + p);
        m1v[k] = __ldg(M1n + p);
        m2v[k] = __ldg(M2n + p);
    }

    float acc[3][PXT];
    #pragma unroll
    for (int c = 0; c < 3; c++)
        #pragma unroll
        for (int k = 0; k < PXT; k++) acc[c][k] = 0.0f;

    #pragma unroll
    for (int img = 0; img < 2; img++) {
        float s = (img == 0) ? 1.0f : -1.0f;
        const float* gb = (img == 0) ? b1 : b2;
        const float* spp = sp + img * 3 * PLANE_W;

        // ── per-pixel state, computed with NO smem dependency ──
        float w00[PXT], w10[PXT], w01[PXT], w11[PXT];
        int offf[PXT], offc[PXT], dy01[PXT];
        bool okf[PXT];

        #pragma unroll
        for (int k = 0; k < PXT; k++) {
            int r = r0 + rsub + k * ROWSUB;
            float x = (float)r   + s * cx[k];
            float y = (float)col + s * cy[k];
            x = fminf(fmaxf(x, 0.001f), (float)IMG_D - 1.001f);
            y = fminf(fmaxf(y, 0.001f), (float)IMG_D - 1.001f);

            int ixf = __float2int_rd(x);
            int ixc = __float2int_ru(x);
            int iyf = __float2int_rd(y);
            int iyc = __float2int_ru(y);

            float wxf = 1.0f - (x - (float)ixf);
            float wxc = 1.0f - ((float)ixc - x);
            float wyf = 1.0f - (y - (float)iyf);
            float wyc = 1.0f - ((float)iyc - y);

            w00[k] = wxf * wyf;
            w10[k] = wxc * wyf;
            w01[k] = wxf * wyc;
            w11[k] = wxc * wyc;

            int rf = ixf - wl;
            int rc = ixc - wl;
            bool ok = ((unsigned)rf < (unsigned)wc) &
                      ((unsigned)rc < (unsigned)wc);
            okf[k]  = ok;
            dy01[k] = iyc - iyf;
            offf[k] = (ok ? rf : ixf) * IMG_D + iyf;
            offc[k] = (ok ? rc : ixc) * IMG_D + iyf;
        }

        // ── channel sections: wait one plane, pure LDS/FFMA burst ──
        #pragma unroll
        for (int c = 0; c < 3; c++) {
            uint32_t mb = mb0 + (img * 3 + c) * 8;
            {
                uint32_t done;
                asm volatile(
                    "{\n\t"
                    ".reg .pred p;\n\t"
                    "mbarrier.try_wait.parity.acquire.cta.shared::cta.b64 p, [%1], 0;\n\t"
                    "selp.b32 %0, 1, 0, p;\n\t"
                    "}"
                    : "=r"(done) : "r"(mb) : "memory");
                if (!done) {
                    asm volatile(
                        "{\n\t"
                        ".reg .pred P1;\n\t"
                        "WL_%=:\n\t"
                        "mbarrier.try_wait.parity.acquire.cta.shared::cta.b64 P1, [%0], 0, 0x989680;\n\t"
                        "@P1 bra.uni WD_%=;\n\t"
                        "bra.uni WL_%=;\n\t"
                        "WD_%=:\n\t"
                        "}"
                        :: "r"(mb) : "memory");
                }
            }

            const float* smc = spp + c * PLANE_W;
            const float* gpc = gb + c * HW;

            #pragma unroll
            for (int k = 0; k < PXT; k++) {
                float v00, v01, v10, v11;
                if (okf[k]) {
                    v00 = smc[offf[k]];
                    v01 = smc[offf[k] + dy01[k]];
                    v10 = smc[offc[k]];
                    v11 = smc[offc[k] + dy01[k]];
                } else {
                    v00 = __ldg(gpc + offf[k]);
                    v01 = __ldg(gpc + offf[k] + dy01[k]);
                    v10 = __ldg(gpc + offc[k]);
                    v11 = __ldg(gpc + offc[k] + dy01[k]);
                }
                float sv = w00[k] * v00;
                sv += w10[k] * v10;
                sv += w01[k] * v01;
                sv += w11[k] * v11;
                float m = (img == 0) ? m1v[k] : m2v[k];
                acc[c][k] += m * sv;
            }
        }
    }

    float* outn = out + (size_t)n * 3 * HW;
    #pragma unroll
    for (int c = 0; c < 3; c++) {
        float* op = outn + c * HW + (r0 + rsub) * IMG_D + col;
        #pragma unroll
        for (int k = 0; k < PXT; k++)
            op[k * ROWSUB * IMG_D] = acc[c][k];
    }
}

extern "C" void kernel_launch(void* const* d_in, const int* in_sizes, int n_in,
                              void* d_out, int out_size)
{
    const float* im1 = (const float*)d_in[0];
    const float* im2 = (const float*)d_in[1];
    const float* C   = (const float*)d_in[2];
    const float* M1  = (const float*)d_in[3];
    const float* M2  = (const float*)d_in[4];
    float* out = (float*)d_out;

    cudaFuncSetAttribute(view_morph14_kernel,
                         cudaFuncAttributeMaxDynamicSharedMemorySize,
                         SMEM_BYTES);

    int blocks = NBATCH * TILES_PER_IMG;  // 1792
    view_morph14_kernel<<<blocks, TPB, SMEM_BYTES>>>(im1, im2, C, M1, M2, out);
}

// round 15
// speedup vs baseline: 1.6987x; 1.6987x over previous
#include <cuda_runtime.h>
#include <cstdint>

#define IMG_D 224
#define HW (IMG_D * IMG_D)
#define NBATCH 64

#define R_TILE 8
#define HALO 4
#define WMAX (R_TILE + 2 * HALO)        // 16 rows staged
#define TILES_PER_IMG (IMG_D / R_TILE)  // 28
#define N_TILES (NBATCH * TILES_PER_IMG) // 1792
#define GRID 296                         // exactly 2 persistent blocks/SM
#define TPB 448                          // 2 sub-rows x 224 cols
#define ROWSUB 2
#define PXT (R_TILE / ROWSUB)            // 4 pixels per thread
#define PLANE_W (WMAX * IMG_D)           // 3584 floats
#define PLANE_BYTES (PLANE_W * 4)        // 14336 B
#define SMEM_BYTES (6 * PLANE_BYTES)     // 86016 B -> 2 blocks/SM

// R11's exact geometry + compute body, made persistent (grid=296, ~6 tiles
// per block) with cross-tile fill prefetch: after a block's im1-gathers for
// tile t complete (syncthreads fence), buffer A is dead, so tile t+296's
// im1 TMA is issued immediately and lands under the im2 compute; likewise
// buffer B after im2. Steady-state waits find data already resident —
// removing the per-block first-fill stall that R11 paid 12x per SM.
// mbarrier phase = tile-iteration parity; re-arm is ordered after all
// threads pass the previous-phase wait via the same syncthreads.

__device__ __forceinline__ void tile_geom(int t, int& n, int& r0, int& wl, int& wc)
{
    n = t / TILES_PER_IMG;
    int tile = t - n * TILES_PER_IMG;
    r0 = tile * R_TILE;
    wl = max(0, r0 - HALO);
    int wh = min(IMG_D - 1, r0 + R_TILE - 1 + HALO);
    wc = wh - wl + 1;
}

__device__ __forceinline__ void issue_img(
    int t, int img, uint32_t mb, uint32_t spb0,
    const float* __restrict__ im1, const float* __restrict__ im2)
{
    int n, r0, wl, wc;
    tile_geom(t, n, r0, wl, wc);
    const float* base = (img == 0 ? im1 : im2) + (size_t)n * 3 * HW;
    uint32_t bytes = (uint32_t)(wc * IMG_D * 4);
    asm volatile("mbarrier.arrive.expect_tx.shared.b64 _, [%0], %1;"
                 :: "r"(mb), "r"(bytes * 3) : "memory");
    #pragma unroll
    for (int pl = 0; pl < 3; pl++) {
        const float* src = base + pl * HW + wl * IMG_D;
        asm volatile(
            "cp.async.bulk.shared::cta.global.mbarrier::complete_tx::bytes"
            " [%0], [%1], %2, [%3];"
            :: "r"(spb0 + (uint32_t)(img * 3 + pl) * PLANE_BYTES), "l"(src),
               "r"(bytes), "r"(mb) : "memory");
    }
}

__device__ __forceinline__ void mbar_wait(uint32_t mb, uint32_t par)
{
    uint32_t done;
    asm volatile(
        "{\n\t"
        ".reg .pred p;\n\t"
        "mbarrier.try_wait.parity.acquire.cta.shared::cta.b64 p, [%1], %2;\n\t"
        "selp.b32 %0, 1, 0, p;\n\t"
        "}"
        : "=r"(done) : "r"(mb), "r"(par) : "memory");
    if (!done) {
        asm volatile(
            "{\n\t"
            ".reg .pred P1;\n\t"
            "WL_%=:\n\t"
            "mbarrier.try_wait.parity.acquire.cta.shared::cta.b64 P1, [%0], %1, 0x989680;\n\t"
            "@P1 bra.uni WD_%=;\n\t"
            "bra.uni WL_%=;\n\t"
            "WD_%=:\n\t"
            "}"
            :: "r"(mb), "r"(par) : "memory");
    }
}

__global__ __launch_bounds__(TPB)
void view_morph15_kernel(
    const float* __restrict__ im1,
    const float* __restrict__ im2,
    const float* __restrict__ C,
    const float* __restrict__ M1,
    const float* __restrict__ M2,
    float* __restrict__ out)
{
    extern __shared__ float sp[];
    __shared__ alignas(8) uint64_t mbar_storage[2];

    int tid = threadIdx.x;
    int col = tid % IMG_D;
    int rsub = tid / IMG_D;

    uint32_t mbA  = (uint32_t)__cvta_generic_to_shared(&mbar_storage[0]);
    uint32_t mbB  = (uint32_t)__cvta_generic_to_shared(&mbar_storage[1]);
    uint32_t spb0 = (uint32_t)__cvta_generic_to_shared(sp);

    if (tid == 0) {
        asm volatile("mbarrier.init.shared.b64 [%0], 1;" :: "r"(mbA) : "memory");
        asm volatile("mbarrier.init.shared.b64 [%0], 1;" :: "r"(mbB) : "memory");
    }
    __syncthreads();

    // prologue: fill both buffers for the first tile
    if (tid == 0) {
        issue_img(blockIdx.x, 0, mbA, spb0, im1, im2);
        issue_img(blockIdx.x, 1, mbB, spb0, im1, im2);
    }

    for (int j = 0, t = blockIdx.x; t < N_TILES; j++, t += GRID) {
        uint32_t par = (uint32_t)(j & 1);
        int n, r0, wl, wc;
        tile_geom(t, n, r0, wl, wc);

        const float* b1 = im1 + (size_t)n * 3 * HW;
        const float* b2 = im2 + (size_t)n * 3 * HW;
        const float* Cn  = C  + (size_t)n * 2 * HW;
        const float* M1n = M1 + (size_t)n * HW;
        const float* M2n = M2 + (size_t)n * HW;

        // prefetch this tile's C/M (overlaps any residual fill)
        float cx[PXT], cy[PXT], m1v[PXT], m2v[PXT];
        #pragma unroll
        for (int k = 0; k < PXT; k++) {
            int r = r0 + rsub + k * ROWSUB;
            int p = r * IMG_D + col;
            cx[k]  = __ldg(Cn + p);
            cy[k]  = __ldg(Cn + HW + p);
            m1v[k] = __ldg(M1n + p);
            m2v[k] = __ldg(M2n + p);
        }

        float acc[3][PXT];
        #pragma unroll
        for (int c = 0; c < 3; c++)
            #pragma unroll
            for (int k = 0; k < PXT; k++) acc[c][k] = 0.0f;

        #pragma unroll
        for (int img = 0; img < 2; img++) {
            mbar_wait(img == 0 ? mbA : mbB, par);

            float s = (img == 0) ? 1.0f : -1.0f;
            const float* gb = (img == 0) ? b1 : b2;
            const float* spp = sp + img * 3 * PLANE_W;

            #pragma unroll
            for (int k = 0; k < PXT; k++) {
                int r = r0 + rsub + k * ROWSUB;
                float fr = (float)r, fc = (float)col;
                float m = (img == 0) ? m1v[k] : m2v[k];

                float x = fr + s * cx[k];
                float y = fc + s * cy[k];
                x = fminf(fmaxf(x, 0.001f), (float)IMG_D - 1.001f);
                y = fminf(fmaxf(y, 0.001f), (float)IMG_D - 1.001f);

                int ixf = __float2int_rd(x);
                int ixc = __float2int_ru(x);
                int iyf = __float2int_rd(y);
                int iyc = __float2int_ru(y);

                float wxf = 1.0f - (x - (float)ixf);
                float wxc = 1.0f - ((float)ixc - x);
                float wyf = 1.0f - (y - (float)iyf);
                float wyc = 1.0f - ((float)iyc - y);

                float w00 = wxf * wyf;
                float w10 = wxc * wyf;
                float w01 = wxf * wyc;
                float w11 = wxc * wyc;

                int rf = ixf - wl;
                int rc = ixc - wl;
                bool ok = ((unsigned)rf < (unsigned)wc) &
                          ((unsigned)rc < (unsigned)wc);

                float v00[3], v10[3], v01[3], v11[3];
                if (ok) {
                    const float* smf = spp + rf * IMG_D;
                    const float* smc = spp + rc * IMG_D;
                    #pragma unroll
                    for (int c = 0; c < 3; c++) {
                        v00[c] = smf[c * PLANE_W + iyf];
                        v01[c] = smf[c * PLANE_W + iyc];
                        v10[c] = smc[c * PLANE_W + iyf];
                        v11[c] = smc[c * PLANE_W + iyc];
                    }
                } else {
                    #pragma unroll
                    for (int c = 0; c < 3; c++) {
                        const float* gf = gb + c * HW + ixf * IMG_D;
                        const float* gc = gb + c * HW + ixc * IMG_D;
                        v00[c] = __ldg(gf + iyf);
                        v01[c] = __ldg(gf + iyc);
                        v10[c] = __ldg(gc + iyf);
                        v11[c] = __ldg(gc + iyc);
                    }
                }

                #pragma unroll
                for (int c = 0; c < 3; c++) {
                    float sv = w00 * v00[c];
                    sv += w10 * v10[c];
                    sv += w01 * v01[c];
                    sv += w11 * v11[c];
                    acc[c][k] += m * sv;
                }
            }

            // buffer for this image is dead: fence readers, then prefetch
            // the NEXT tile's same-image planes into it (flips phase).
            __syncthreads();
            int tn = t + GRID;
            if (tid == 0 && tn < N_TILES)
                issue_img(tn, img, img == 0 ? mbA : mbB, spb0, im1, im2);
        }

        float* outn = out + (size_t)n * 3 * HW;
        #pragma unroll
        for (int c = 0; c < 3; c++) {
            float* op = outn + c * HW + (r0 + rsub) * IMG_D + col;
            #pragma unroll
            for (int k = 0; k < PXT; k++)
                op[k * ROWSUB * IMG_D] = acc[c][k];
        }
    }
}

extern "C" void kernel_launch(void* const* d_in, const int* in_sizes, int n_in,
                              void* d_out, int out_size)
{
    const float* im1 = (const float*)d_in[0];
    const float* im2 = (const float*)d_in[1];
    const float* C   = (const float*)d_in[2];
    const float* M1  = (const float*)d_in[3];
    const float* M2  = (const float*)d_in[4];
    float* out = (float*)d_out;

    cudaFuncSetAttribute(view_morph15_kernel,
                         cudaFuncAttributeMaxDynamicSharedMemorySize,
                         SMEM_BYTES);

    view_morph15_kernel<<<GRID, TPB, SMEM_BYTES>>>(im1, im2, C, M1, M2, out);
}

// round 16
// speedup vs baseline: 1.8840x; 1.1091x over previous
#include <cuda_runtime.h>
#include <cstdint>

#define IMG_D 224
#define HW (IMG_D * IMG_D)
#define NBATCH 64

#define R_TILE 8
#define HALO 4
#define WMAX (R_TILE + 2 * HALO)        // 16 rows staged
#define TILES_PER_IMG (IMG_D / R_TILE)  // 28
#define TPB 448                         // 2 sub-rows x 224 cols
#define ROWSUB 2
#define PXT (R_TILE / ROWSUB)           // 4 pixels per thread
#define PLANE_W (WMAX * IMG_D)          // 3584 floats
#define PLANE_BYTES (PLANE_W * 4)       // 14336 B
#define SMEM_BYTES (6 * PLANE_BYTES)    // 86016 B -> 2 blocks/SM

// Champion R11 design: split-image TMA staging (im1's 3 plane windows ->
// mbar0, im2's -> mbar1), img-outer compute that hides im2's fill behind
// im1's gathers, HALO=4 (16-row windows, fallback P~6e-5), conflict-
// tolerant LDS gathers. Single change vs R11: tid0 inits mbarriers and
// issues ALL SIX TMA copies BEFORE the __syncthreads (safe: program order
// within tid0; the barrier only protects other threads' first try_wait),
// taking the barrier-release latency off the fill critical path.
__global__ __launch_bounds__(TPB)
void view_morph16_kernel(
    const float* __restrict__ im1,
    const float* __restrict__ im2,
    const float* __restrict__ C,
    const float* __restrict__ M1,
    const float* __restrict__ M2,
    float* __restrict__ out)
{
    extern __shared__ float sp[];
    __shared__ alignas(8) uint64_t mbar_storage[2];

    int blk = blockIdx.x;
    int n = blk / TILES_PER_IMG;
    int tile = blk - n * TILES_PER_IMG;
    int r0 = tile * R_TILE;

    int wl = max(0, r0 - HALO);
    int wh = min(IMG_D - 1, r0 + R_TILE - 1 + HALO);
    int wc = wh - wl + 1;

    int tid = threadIdx.x;
    int col = tid % IMG_D;
    int rsub = tid / IMG_D;

    const float* b1 = im1 + (size_t)n * 3 * HW;
    const float* b2 = im2 + (size_t)n * 3 * HW;

    uint32_t mbar0 = (uint32_t)__cvta_generic_to_shared(&mbar_storage[0]);
    uint32_t mbar1 = (uint32_t)__cvta_generic_to_shared(&mbar_storage[1]);
    uint32_t spb0  = (uint32_t)__cvta_generic_to_shared(sp);

    if (tid == 0) {
        asm volatile("mbarrier.init.shared.b64 [%0], 1;" :: "r"(mbar0) : "memory");
        asm volatile("mbarrier.init.shared.b64 [%0], 1;" :: "r"(mbar1) : "memory");
        // fence init -> async proxy before TMA completion targets the barriers
        asm volatile("fence.proxy.async.shared::cta;" ::: "memory");

        uint32_t copy_bytes = (uint32_t)(wc * IMG_D * 4);
        asm volatile("mbarrier.arrive.expect_tx.shared.b64 _, [%0], %1;"
                     :: "r"(mbar0), "r"(copy_bytes * 3) : "memory");
        asm volatile("mbarrier.arrive.expect_tx.shared.b64 _, [%0], %1;"
                     :: "r"(mbar1), "r"(copy_bytes * 3) : "memory");
        #pragma unroll
        for (int pl = 0; pl < 3; pl++) {     // im1 planes -> mbar0
            const float* src = b1 + pl * HW + wl * IMG_D;
            asm volatile(
                "cp.async.bulk.shared::cta.global.mbarrier::complete_tx::bytes"
                " [%0], [%1], %2, [%3];"
                :: "r"(spb0 + pl * PLANE_BYTES), "l"(src),
                   "r"(copy_bytes), "r"(mbar0) : "memory");
        }
        #pragma unroll
        for (int pl = 0; pl < 3; pl++) {     // im2 planes -> mbar1
            const float* src = b2 + pl * HW + wl * IMG_D;
            asm volatile(
                "cp.async.bulk.shared::cta.global.mbarrier::complete_tx::bytes"
                " [%0], [%1], %2, [%3];"
                :: "r"(spb0 + (pl + 3) * PLANE_BYTES), "l"(src),
                   "r"(copy_bytes), "r"(mbar1) : "memory");
        }
    }
    __syncthreads();   // other threads must not try_wait before init

    // ── prefetch C/M while TMA runs ──
    const float* Cn  = C  + (size_t)n * 2 * HW;
    const float* M1n = M1 + (size_t)n * HW;
    const float* M2n = M2 + (size_t)n * HW;

    float cx[PXT], cy[PXT], m1v[PXT], m2v[PXT];
    #pragma unroll
    for (int k = 0; k < PXT; k++) {
        int r = r0 + rsub + k * ROWSUB;
        int p = r * IMG_D + col;
        cx[k]  = __ldg(Cn + p);
        cy[k]  = __ldg(Cn + HW + p);
        m1v[k] = __ldg(M1n + p);
        m2v[k] = __ldg(M2n + p);
    }

    float acc[3][PXT];
    #pragma unroll
    for (int c = 0; c < 3; c++)
        #pragma unroll
        for (int k = 0; k < PXT; k++) acc[c][k] = 0.0f;

    #pragma unroll
    for (int img = 0; img < 2; img++) {
        uint32_t mbar = (img == 0) ? mbar0 : mbar1;
        {
            uint32_t done;
            asm volatile(
                "{\n\t"
                ".reg .pred p;\n\t"
                "mbarrier.try_wait.parity.acquire.cta.shared::cta.b64 p, [%1], 0;\n\t"
                "selp.b32 %0, 1, 0, p;\n\t"
                "}"
                : "=r"(done) : "r"(mbar) : "memory");
            if (!done) {
                asm volatile(
                    "{\n\t"
                    ".reg .pred P1;\n\t"
                    "WL_%=:\n\t"
                    "mbarrier.try_wait.parity.acquire.cta.shared::cta.b64 P1, [%0], 0, 0x989680;\n\t"
                    "@P1 bra.uni WD_%=;\n\t"
                    "bra.uni WL_%=;\n\t"
                    "WD_%=:\n\t"
                    "}"
                    :: "r"(mbar) : "memory");
            }
        }

        float s = (img == 0) ? 1.0f : -1.0f;
        const float* gb = (img == 0) ? b1 : b2;
        const float* spp = sp + img * 3 * PLANE_W;

        #pragma unroll
        for (int k = 0; k < PXT; k++) {
            int r = r0 + rsub + k * ROWSUB;
            float fr = (float)r, fc = (float)col;
            float m = (img == 0) ? m1v[k] : m2v[k];

            float x = fr + s * cx[k];
            float y = fc + s * cy[k];
            x = fminf(fmaxf(x, 0.001f), (float)IMG_D - 1.001f);
            y = fminf(fmaxf(y, 0.001f), (float)IMG_D - 1.001f);

            int ixf = __float2int_rd(x);
            int ixc = __float2int_ru(x);
            int iyf = __float2int_rd(y);
            int iyc = __float2int_ru(y);

            float wxf = 1.0f - (x - (float)ixf);
            float wxc = 1.0f - ((float)ixc - x);
            float wyf = 1.0f - (y - (float)iyf);
            float wyc = 1.0f - ((float)iyc - y);

            float w00 = wxf * wyf;
            float w10 = wxc * wyf;
            float w01 = wxf * wyc;
            float w11 = wxc * wyc;

            int rf = ixf - wl;
            int rc = ixc - wl;
            bool ok = ((unsigned)rf < (unsigned)wc) &
                      ((unsigned)rc < (unsigned)wc);

            float v00[3], v10[3], v01[3], v11[3];
            if (ok) {
                const float* smf = spp + rf * IMG_D;
                const float* smc = spp + rc * IMG_D;
                #pragma unroll
                for (int c = 0; c < 3; c++) {
                    v00[c] = smf[c * PLANE_W + iyf];
                    v01[c] = smf[c * PLANE_W + iyc];
                    v10[c] = smc[c * PLANE_W + iyf];
                    v11[c] = smc[c * PLANE_W + iyc];
                }
            } else {
                #pragma unroll
                for (int c = 0; c < 3; c++) {
                    const float* gf = gb + c * HW + ixf * IMG_D;
                    const float* gc = gb + c * HW + ixc * IMG_D;
                    v00[c] = __ldg(gf + iyf);
                    v01[c] = __ldg(gf + iyc);
                    v10[c] = __ldg(gc + iyf);
                    v11[c] = __ldg(gc + iyc);
                }
            }

            #pragma unroll
            for (int c = 0; c < 3; c++) {
                float sv = w00 * v00[c];
                sv += w10 * v10[c];
                sv += w01 * v01[c];
                sv += w11 * v11[c];
                acc[c][k] += m * sv;
            }
        }
    }

    float* outn = out + (size_t)n * 3 * HW;
    #pragma unroll
    for (int c = 0; c < 3; c++) {
        float* op = outn + c * HW + (r0 + rsub) * IMG_D + col;
        #pragma unroll
        for (int k = 0; k < PXT; k++)
            op[k * ROWSUB * IMG_D] = acc[c][k];
    }
}

extern "C" void kernel_launch(void* const* d_in, const int* in_sizes, int n_in,
                              void* d_out, int out_size)
{
    const float* im1 = (const float*)d_in[0];
    const float* im2 = (const float*)d_in[1];
    const float* C   = (const float*)d_in[2];
    const float* M1  = (const float*)d_in[3];
    const float* M2  = (const float*)d_in[4];
    float* out = (float*)d_out;

    cudaFuncSetAttribute(view_morph16_kernel,
                         cudaFuncAttributeMaxDynamicSharedMemorySize,
                         SMEM_BYTES);

    int blocks = NBATCH * TILES_PER_IMG;  // 1792
    view_morph16_kernel<<<blocks, TPB, SMEM_BYTES>>>(im1, im2, C, M1, M2, out);
}

// round 17
// speedup vs baseline: 1.8873x; 1.0017x over previous
#include <cuda_runtime.h>
#include <cstdint>

#define IMG_D 224
#define HW (IMG_D * IMG_D)
#define NBATCH 64

#define R_TILE 8
#define HALO 4
#define WMAX (R_TILE + 2 * HALO)        // 16 rows staged
#define TILES_PER_IMG (IMG_D / R_TILE)  // 28
#define TPB 448                         // 2 sub-rows x 224 cols
#define ROWSUB 2
#define PXT (R_TILE / ROWSUB)           // 4 pixels per thread
#define PLANE_W (WMAX * IMG_D)          // 3584 floats
#define PLANE_BYTES (PLANE_W * 4)       // 14336 B
#define SMEM_BYTES (6 * PLANE_BYTES)    // 86016 B -> 2 blocks/SM

// FINAL (champion R11): block = (n, 8-row band). Six channel-plane windows
// (16 rows, 4-row halo) staged via cp.async.bulk — im1's three planes
// signal mbar0, im2's signal mbar1. tid0 issues after one barrier while the
// other 447 threads prefetch C/M. The img-outer loop computes all im1
// contributions the moment its 43KB lands, hiding im2's fill latency.
// Gathers are LDS from the staged windows (bank = column+jitter; conflicts
// are data-intrinsic and at their floor); out-of-window corners (P~6e-5)
// fall back to global loads. Per-element arithmetic order matches the
// reference exactly (im1 term then im2 term; clip/floor/ceil weights).
__global__ __launch_bounds__(TPB)
void view_morph_final_kernel(
    const float* __restrict__ im1,
    const float* __restrict__ im2,
    const float* __restrict__ C,
    const float* __restrict__ M1,
    const float* __restrict__ M2,
    float* __restrict__ out)
{
    extern __shared__ float sp[];
    __shared__ alignas(8) uint64_t mbar_storage[2];

    int blk = blockIdx.x;
    int n = blk / TILES_PER_IMG;
    int tile = blk - n * TILES_PER_IMG;
    int r0 = tile * R_TILE;

    int wl = max(0, r0 - HALO);
    int wh = min(IMG_D - 1, r0 + R_TILE - 1 + HALO);
    int wc = wh - wl + 1;

    int tid = threadIdx.x;
    int col = tid % IMG_D;
    int rsub = tid / IMG_D;

    const float* b1 = im1 + (size_t)n * 3 * HW;
    const float* b2 = im2 + (size_t)n * 3 * HW;

    uint32_t mbar0 = (uint32_t)__cvta_generic_to_shared(&mbar_storage[0]);
    uint32_t mbar1 = (uint32_t)__cvta_generic_to_shared(&mbar_storage[1]);
    uint32_t spb0  = (uint32_t)__cvta_generic_to_shared(sp);

    if (tid == 0) {
        asm volatile("mbarrier.init.shared.b64 [%0], 1;" :: "r"(mbar0) : "memory");
        asm volatile("mbarrier.init.shared.b64 [%0], 1;" :: "r"(mbar1) : "memory");
    }
    __syncthreads();

    if (tid == 0) {
        uint32_t copy_bytes = (uint32_t)(wc * IMG_D * 4);
        asm volatile("mbarrier.arrive.expect_tx.shared.b64 _, [%0], %1;"
                     :: "r"(mbar0), "r"(copy_bytes * 3) : "memory");
        asm volatile("mbarrier.arrive.expect_tx.shared.b64 _, [%0], %1;"
                     :: "r"(mbar1), "r"(copy_bytes * 3) : "memory");
        #pragma unroll
        for (int pl = 0; pl < 3; pl++) {     // im1 planes -> mbar0
            const float* src = b1 + pl * HW + wl * IMG_D;
            asm volatile(
                "cp.async.bulk.shared::cta.global.mbarrier::complete_tx::bytes"
                " [%0], [%1], %2, [%3];"
                :: "r"(spb0 + pl * PLANE_BYTES), "l"(src),
                   "r"(copy_bytes), "r"(mbar0) : "memory");
        }
        #pragma unroll
        for (int pl = 0; pl < 3; pl++) {     // im2 planes -> mbar1
            const float* src = b2 + pl * HW + wl * IMG_D;
            asm volatile(
                "cp.async.bulk.shared::cta.global.mbarrier::complete_tx::bytes"
                " [%0], [%1], %2, [%3];"
                :: "r"(spb0 + (pl + 3) * PLANE_BYTES), "l"(src),
                   "r"(copy_bytes), "r"(mbar1) : "memory");
        }
    }

    // ── prefetch C/M while TMA runs ──
    const float* Cn  = C  + (size_t)n * 2 * HW;
    const float* M1n = M1 + (size_t)n * HW;
    const float* M2n = M2 + (size_t)n * HW;

    float cx[PXT], cy[PXT], m1v[PXT], m2v[PXT];
    #pragma unroll
    for (int k = 0; k < PXT; k++) {
        int r = r0 + rsub + k * ROWSUB;
        int p = r * IMG_D + col;
        cx[k]  = __ldg(Cn + p);
        cy[k]  = __ldg(Cn + HW + p);
        m1v[k] = __ldg(M1n + p);
        m2v[k] = __ldg(M2n + p);
    }

    float acc[3][PXT];
    #pragma unroll
    for (int c = 0; c < 3; c++)
        #pragma unroll
        for (int k = 0; k < PXT; k++) acc[c][k] = 0.0f;

    #pragma unroll
    for (int img = 0; img < 2; img++) {
        uint32_t mbar = (img == 0) ? mbar0 : mbar1;
        {
            uint32_t done;
            asm volatile(
                "{\n\t"
                ".reg .pred p;\n\t"
                "mbarrier.try_wait.parity.acquire.cta.shared::cta.b64 p, [%1], 0;\n\t"
                "selp.b32 %0, 1, 0, p;\n\t"
                "}"
                : "=r"(done) : "r"(mbar) : "memory");
            if (!done) {
                asm volatile(
                    "{\n\t"
                    ".reg .pred P1;\n\t"
                    "WL_%=:\n\t"
                    "mbarrier.try_wait.parity.acquire.cta.shared::cta.b64 P1, [%0], 0, 0x989680;\n\t"
                    "@P1 bra.uni WD_%=;\n\t"
                    "bra.uni WL_%=;\n\t"
                    "WD_%=:\n\t"
                    "}"
                    :: "r"(mbar) : "memory");
            }
        }

        float s = (img == 0) ? 1.0f : -1.0f;
        const float* gb = (img == 0) ? b1 : b2;
        const float* spp = sp + img * 3 * PLANE_W;

        #pragma unroll
        for (int k = 0; k < PXT; k++) {
            int r = r0 + rsub + k * ROWSUB;
            float fr = (float)r, fc = (float)col;
            float m = (img == 0) ? m1v[k] : m2v[k];

            float x = fr + s * cx[k];
            float y = fc + s * cy[k];
            x = fminf(fmaxf(x, 0.001f), (float)IMG_D - 1.001f);
            y = fminf(fmaxf(y, 0.001f), (float)IMG_D - 1.001f);

            int ixf = __float2int_rd(x);
            int ixc = __float2int_ru(x);
            int iyf = __float2int_rd(y);
            int iyc = __float2int_ru(y);

            float wxf = 1.0f - (x - (float)ixf);
            float wxc = 1.0f - ((float)ixc - x);
            float wyf = 1.0f - (y - (float)iyf);
            float wyc = 1.0f - ((float)iyc - y);

            float w00 = wxf * wyf;
            float w10 = wxc * wyf;
            float w01 = wxf * wyc;
            float w11 = wxc * wyc;

            int rf = ixf - wl;
            int rc = ixc - wl;
            bool ok = ((unsigned)rf < (unsigned)wc) &
                      ((unsigned)rc < (unsigned)wc);

            float v00[3], v10[3], v01[3], v11[3];
            if (ok) {
                const float* smf = spp + rf * IMG_D;
                const float* smc = spp + rc * IMG_D;
                #pragma unroll
                for (int c = 0; c < 3; c++) {
                    v00[c] = smf[c * PLANE_W + iyf];
                    v01[c] = smf[c * PLANE_W + iyc];
                    v10[c] = smc[c * PLANE_W + iyf];
                    v11[c] = smc[c * PLANE_W + iyc];
                }
            } else {
                #pragma unroll
                for (int c = 0; c < 3; c++) {
                    const float* gf = gb + c * HW + ixf * IMG_D;
                    const float* gc = gb + c * HW + ixc * IMG_D;
                    v00[c] = __ldg(gf + iyf);
                    v01[c] = __ldg(gf + iyc);
                    v10[c] = __ldg(gc + iyf);
                    v11[c] = __ldg(gc + iyc);
                }
            }

            #pragma unroll
            for (int c = 0; c < 3; c++) {
                float sv = w00 * v00[c];
                sv += w10 * v10[c];
                sv += w01 * v01[c];
                sv += w11 * v11[c];
                acc[c][k] += m * sv;
            }
        }
    }

    float* outn = out + (size_t)n * 3 * HW;
    #pragma unroll
    for (int c = 0; c < 3; c++) {
        float* op = outn + c * HW + (r0 + rsub) * IMG_D + col;
        #pragma unroll
        for (int k = 0; k < PXT; k++)
            op[k * ROWSUB * IMG_D] = acc[c][k];
    }
}

extern "C" void kernel_launch(void* const* d_in, const int* in_sizes, int n_in,
                              void* d_out, int out_size)
{
    const float* im1 = (const float*)d_in[0];
    const float* im2 = (const float*)d_in[1];
    const float* C   = (const float*)d_in[2];
    const float* M1  = (const float*)d_in[3];
    const float* M2  = (const float*)d_in[4];
    float* out = (float*)d_out;

    cudaFuncSetAttribute(view_morph_final_kernel,
                         cudaFuncAttributeMaxDynamicSharedMemorySize,
                         SMEM_BYTES);

    int blocks = NBATCH * TILES_PER_IMG;  // 1792
    view_morph_final_kernel<<<blocks, TPB, SMEM_BYTES>>>(im1, im2, C, M1, M2, out);
}